// round 2
// baseline (speedup 1.0000x reference)
#include <cuda_runtime.h>
#include <cuda_fp16.h>
#include <cstdint>

// ============================================================================
// SubtractionGaussian: out[b,h,i,j] = ||q_i||^2 + ||k_j||^2 - 2 q_i . k_j
// B*H = 32, Lq = Lk = 2048, D = 64, fp32 in/out.
//
// Base-ISA design (bench targets compute_103, no tcgen05):
//   - fp16 mma.sync.m16n8k16 for the q.k term (rel err ~1e-4, under 1e-3 gate)
//   - ||q||^2, ||k||^2 in exact fp32 during load
//   - 128x128 tile per CTA, 256 threads, 8 warps (4 row-groups x 2 col-groups)
// ============================================================================

#define LQ 2048
#define LK 2048
#define DDIM 64
#define TILE_M 128
#define TILE_N 128
#define THREADS 256
#define SMEM_PAD 8          // halfs of padding per row (16B, keeps ldmatrix-free lds aligned)
#define ROWLEN (DDIM + SMEM_PAD)   // 72 halfs = 144 B

__device__ __forceinline__ void mma16816(float* d, const uint32_t* a,
                                         uint32_t b0, uint32_t b1) {
    asm volatile(
        "mma.sync.aligned.m16n8k16.row.col.f32.f16.f16.f32 "
        "{%0,%1,%2,%3}, {%4,%5,%6,%7}, {%8,%9}, {%0,%1,%2,%3};"
        : "+f"(d[0]), "+f"(d[1]), "+f"(d[2]), "+f"(d[3])
        : "r"(a[0]), "r"(a[1]), "r"(a[2]), "r"(a[3]), "r"(b0), "r"(b1));
}

__global__ void __launch_bounds__(THREADS, 2)
subgauss_kernel(const float* __restrict__ q,   // [BH, Lq, D]
                const float* __restrict__ k,   // [BH, D, Lk]
                float* __restrict__ out)       // [BH, Lq, Lk]
{
    __shared__ __half Qs[TILE_M][ROWLEN];      // Qs[i][c]
    __shared__ __half Ks[TILE_N][ROWLEN];      // Ks[j][c]  (transposed from input)
    __shared__ float q2p[THREADS];
    __shared__ float k2p[THREADS];
    __shared__ float q2s[TILE_M];
    __shared__ float k2s[TILE_N];

    const int tid = threadIdx.x;
    const int lane = tid & 31;
    const int wid = tid >> 5;

    const int bh = blockIdx.z;
    const int i0 = blockIdx.y * TILE_M;
    const int j0 = blockIdx.x * TILE_N;

    // ---- Load Q tile: thread pair per row, 32 floats each, fp32 sumsq. ----
    {
        const int r = tid >> 1;
        const int ch = (tid & 1) * 32;
        const float4* src = reinterpret_cast<const float4*>(
            q + ((size_t)bh * LQ + (size_t)(i0 + r)) * DDIM + ch);
        float acc = 0.0f;
#pragma unroll
        for (int it = 0; it < 8; it++) {
            float4 v = src[it];
            acc += v.x * v.x + v.y * v.y + v.z * v.z + v.w * v.w;
            __half2 h0 = __floats2half2_rn(v.x, v.y);
            __half2 h1 = __floats2half2_rn(v.z, v.w);
            *reinterpret_cast<__half2*>(&Qs[r][ch + it * 4])     = h0;
            *reinterpret_cast<__half2*>(&Qs[r][ch + it * 4 + 2]) = h1;
        }
        q2p[tid] = acc;
    }

    // ---- Load K tile (transpose to Ks[j][c]): coalesced over j. ----
    {
        const int j = tid & 127;
        const int c0 = tid >> 7;          // 0 or 1
        const float* kb = k + (size_t)bh * DDIM * LK + (size_t)j0 + j;
        float acc = 0.0f;
#pragma unroll
        for (int rep = 0; rep < 32; rep++) {
            int c = c0 + rep * 2;
            float v = kb[(size_t)c * LK];
            acc += v * v;
            Ks[j][c] = __float2half_rn(v);
        }
        k2p[tid] = acc;
    }
    __syncthreads();

    if (tid < 128) {
        q2s[tid] = q2p[2 * tid] + q2p[2 * tid + 1];
        k2s[tid] = k2p[tid] + k2p[tid + 128];
    }
    __syncthreads();

    // ---- Mainloop: warp (wm, wn) computes rows [wm*32, +32) x cols [wn*64, +64). ----
    const int wm = wid & 3;
    const int wn = wid >> 2;
    const int gq = lane >> 2;     // 0..7
    const int tq = lane & 3;      // 0..3
    const int mbase = wm * 32;
    const int nbase = wn * 64;

    float acc[2][8][4];
#pragma unroll
    for (int mm = 0; mm < 2; mm++)
#pragma unroll
        for (int nn = 0; nn < 8; nn++)
#pragma unroll
            for (int r = 0; r < 4; r++)
                acc[mm][nn][r] = 0.0f;

#pragma unroll
    for (int ks = 0; ks < 4; ks++) {
        const int kc = ks * 16 + tq * 2;

        uint32_t A[2][4];
#pragma unroll
        for (int mm = 0; mm < 2; mm++) {
            const int r = mbase + mm * 16 + gq;
            A[mm][0] = *reinterpret_cast<const uint32_t*>(&Qs[r][kc]);
            A[mm][1] = *reinterpret_cast<const uint32_t*>(&Qs[r + 8][kc]);
            A[mm][2] = *reinterpret_cast<const uint32_t*>(&Qs[r][kc + 8]);
            A[mm][3] = *reinterpret_cast<const uint32_t*>(&Qs[r + 8][kc + 8]);
        }
#pragma unroll
        for (int nn = 0; nn < 8; nn++) {
            const int j = nbase + nn * 8 + gq;
            uint32_t B0 = *reinterpret_cast<const uint32_t*>(&Ks[j][kc]);
            uint32_t B1 = *reinterpret_cast<const uint32_t*>(&Ks[j][kc + 8]);
#pragma unroll
            for (int mm = 0; mm < 2; mm++) {
                mma16816(acc[mm][nn], A[mm], B0, B1);
            }
        }
    }

    // ---- Epilogue: out = q2 + k2 - 2*qk, float2 stores (dense 32B sectors). ----
#pragma unroll
    for (int mm = 0; mm < 2; mm++) {
        const int r0 = mbase + mm * 16 + gq;
        const float q2a = q2s[r0];
        const float q2b = q2s[r0 + 8];
        float* row0 = out + ((size_t)bh * LQ + (size_t)(i0 + r0)) * LK + j0;
        float* row1 = row0 + (size_t)8 * LK;
#pragma unroll
        for (int nn = 0; nn < 8; nn++) {
            const int cl = nbase + nn * 8 + tq * 2;
            const float k2a = k2s[cl];
            const float k2b = k2s[cl + 1];
            float2 v0, v1;
            v0.x = q2a + k2a - 2.0f * acc[mm][nn][0];
            v0.y = q2a + k2b - 2.0f * acc[mm][nn][1];
            v1.x = q2b + k2a - 2.0f * acc[mm][nn][2];
            v1.y = q2b + k2b - 2.0f * acc[mm][nn][3];
            *reinterpret_cast<float2*>(row0 + cl) = v0;
            *reinterpret_cast<float2*>(row1 + cl) = v1;
        }
    }
}

// ---------------- Launch ----------------

extern "C" void kernel_launch(void* const* d_in, const int* in_sizes, int n_in,
                              void* d_out, int out_size) {
    const float* q = (const float*)d_in[0];   // [4,8,2048,64]
    const float* k = (const float*)d_in[1];   // [4,8,64,2048]
    float* out = (float*)d_out;               // [4,8,2048,2048]
    (void)in_sizes; (void)n_in; (void)out_size;

    dim3 grid(LK / TILE_N, LQ / TILE_M, 32);  // 16 x 16 x 32
    subgauss_kernel<<<grid, THREADS>>>(q, k, out);
}

// round 3
// speedup vs baseline: 1.2887x; 1.2887x over previous
#include <cuda_runtime.h>
#include <cuda_fp16.h>
#include <cstdint>

// ============================================================================
// SubtractionGaussian: out[b,h,i,j] = ||q_i||^2 + ||k_j||^2 - 2 q_i . k_j
// B*H = 32, Lq = Lk = 2048, D = 64, fp32 in/out.
//
// R3: L1-wavefront diet.
//  - coalesced 128B-contiguous LDG for Q and K
//  - K kept c-major in smem (coalesced STS), B frags via ldmatrix.x4.trans
//  - ldmatrix.x4 for A frags
//  - shuffle-transposed epilogue -> float4 STG (64B/row contiguous)
// ============================================================================

#define LQ 2048
#define LK 2048
#define DDIM 64
#define TILE_M 128
#define TILE_N 128
#define THREADS 256

#define QROW 72        // halfs per Qs row (144B; granule stride 9 == 1 mod 8 -> ldmatrix conflict-free)
#define KROW 136       // halfs per Ks row (272B; granule stride 17 == 1 mod 8 -> conflict-free)

__device__ __forceinline__ void mma16816(float* d, const uint32_t* a,
                                         uint32_t b0, uint32_t b1) {
    asm volatile(
        "mma.sync.aligned.m16n8k16.row.col.f32.f16.f16.f32 "
        "{%0,%1,%2,%3}, {%4,%5,%6,%7}, {%8,%9}, {%0,%1,%2,%3};"
        : "+f"(d[0]), "+f"(d[1]), "+f"(d[2]), "+f"(d[3])
        : "r"(a[0]), "r"(a[1]), "r"(a[2]), "r"(a[3]), "r"(b0), "r"(b1));
}

__device__ __forceinline__ void ldmatrix_x4(uint32_t* r, uint32_t addr) {
    asm volatile("ldmatrix.sync.aligned.m8n8.x4.shared.b16 {%0,%1,%2,%3}, [%4];"
                 : "=r"(r[0]), "=r"(r[1]), "=r"(r[2]), "=r"(r[3]) : "r"(addr));
}

__device__ __forceinline__ void ldmatrix_x4_trans(uint32_t* r, uint32_t addr) {
    asm volatile("ldmatrix.sync.aligned.m8n8.x4.trans.shared.b16 {%0,%1,%2,%3}, [%4];"
                 : "=r"(r[0]), "=r"(r[1]), "=r"(r[2]), "=r"(r[3]) : "r"(addr));
}

__global__ void __launch_bounds__(THREADS, 2)
subgauss_kernel(const float* __restrict__ q,   // [BH, Lq, D]
                const float* __restrict__ k,   // [BH, D, Lk]
                float* __restrict__ out)       // [BH, Lq, Lk]
{
    __shared__ __half Qs[TILE_M][QROW];   // [i][c]
    __shared__ __half Ks[DDIM][KROW];     // [c][j]  (same orientation as global)
    __shared__ float q2s[TILE_M];
    __shared__ float k2s[TILE_N];

    const int tid = threadIdx.x;
    const int lane = tid & 31;
    const int wid = tid >> 5;

    const int bh = blockIdx.z;
    const int i0 = blockIdx.y * TILE_M;
    const int j0 = blockIdx.x * TILE_N;

    // ---- Q load: 8 threads per row, 128B-contiguous lane groups. ----
    {
        const int seg = tid & 7;           // 8 threads per row
        const int rbase = tid >> 3;        // 0..31
#pragma unroll
        for (int pass = 0; pass < 4; pass++) {
            const int r = rbase + pass * 32;
            const float* qrow = q + ((size_t)bh * LQ + (size_t)(i0 + r)) * DDIM;
            float partial = 0.0f;
#pragma unroll
            for (int a = 0; a < 2; a++) {
                const int c = a * 32 + seg * 4;               // lanes seg: 128B contiguous
                float4 v = *reinterpret_cast<const float4*>(qrow + c);
                partial += v.x * v.x + v.y * v.y + v.z * v.z + v.w * v.w;
                __half2 h01 = __floats2half2_rn(v.x, v.y);
                __half2 h23 = __floats2half2_rn(v.z, v.w);
                uint2 u;
                u.x = *reinterpret_cast<uint32_t*>(&h01);
                u.y = *reinterpret_cast<uint32_t*>(&h23);
                *reinterpret_cast<uint2*>(&Qs[r][c]) = u;
            }
            // exact ||q||^2: reduce over the 8 threads of this row
            partial += __shfl_down_sync(0xffffffffu, partial, 4, 8);
            partial += __shfl_down_sync(0xffffffffu, partial, 2, 8);
            partial += __shfl_down_sync(0xffffffffu, partial, 1, 8);
            if (seg == 0) q2s[r] = partial;
        }
    }

    // ---- K load: c-major, fully coalesced both ends. ----
    {
        const int seg = tid & 7;
        const int cbase = tid >> 3;        // 0..31
#pragma unroll
        for (int pass = 0; pass < 2; pass++) {
            const int c = cbase + pass * 32;
            const float* krow = k + ((size_t)bh * DDIM + (size_t)c) * LK + j0;
#pragma unroll
            for (int a = 0; a < 4; a++) {
                const int j = a * 32 + seg * 4;
                float4 v = *reinterpret_cast<const float4*>(krow + j);
                __half2 h01 = __floats2half2_rn(v.x, v.y);
                __half2 h23 = __floats2half2_rn(v.z, v.w);
                uint2 u;
                u.x = *reinterpret_cast<uint32_t*>(&h01);
                u.y = *reinterpret_cast<uint32_t*>(&h23);
                *reinterpret_cast<uint2*>(&Ks[c][j]) = u;
            }
        }
    }
    __syncthreads();

    // ---- k2 from fp16 tile (error contribution ~1e-5 rel, conflict-free LDS). ----
    if (tid < TILE_N) {
        float s = 0.0f;
#pragma unroll 16
        for (int c = 0; c < DDIM; c++) {
            float v = __half2float(Ks[c][tid]);
            s = fmaf(v, v, s);
        }
        k2s[tid] = s;
    }
    __syncthreads();

    // ---- Mainloop: warp (wm,wn) -> rows [wm*32,+32) x cols [wn*64,+64). ----
    const int wm = wid & 3;
    const int wn = wid >> 2;
    const int mbase = wm * 32;
    const int nbase = wn * 64;
    const int g = lane >> 3;      // ldmatrix quadrant
    const int lr = lane & 7;      // ldmatrix row

    float acc[2][8][4];
#pragma unroll
    for (int mm = 0; mm < 2; mm++)
#pragma unroll
        for (int nn = 0; nn < 8; nn++)
#pragma unroll
            for (int r = 0; r < 4; r++)
                acc[mm][nn][r] = 0.0f;

#pragma unroll
    for (int ks = 0; ks < 4; ks++) {
        uint32_t A[2][4];
#pragma unroll
        for (int mm = 0; mm < 2; mm++) {
            uint32_t addr = (uint32_t)__cvta_generic_to_shared(
                &Qs[mbase + mm * 16 + (g & 1) * 8 + lr][ks * 16 + (g >> 1) * 8]);
            ldmatrix_x4(A[mm], addr);
        }
#pragma unroll
        for (int e = 0; e < 4; e++) {
            uint32_t B[4];
            uint32_t addr = (uint32_t)__cvta_generic_to_shared(
                &Ks[ks * 16 + (g & 1) * 8 + lr][nbase + e * 16 + (g >> 1) * 8]);
            ldmatrix_x4_trans(B, addr);
            mma16816(acc[0][2 * e],     A[0], B[0], B[1]);
            mma16816(acc[1][2 * e],     A[1], B[0], B[1]);
            mma16816(acc[0][2 * e + 1], A[0], B[2], B[3]);
            mma16816(acc[1][2 * e + 1], A[1], B[2], B[3]);
        }
    }

    // ---- Epilogue: 4-lane shuffle transpose -> float4 STG (64B/row). ----
    const int gq = lane >> 2;
    const int tq = lane & 3;
    const int d1 = (gq << 2) | ((2 * tq) & 3);   // donor lanes d1, d1+1

#pragma unroll
    for (int mm = 0; mm < 2; mm++) {
#pragma unroll
        for (int h = 0; h < 2; h++) {
            const int rl = mbase + mm * 16 + h * 8 + gq;
            const float q2v = q2s[rl];
            float* orow = out + ((size_t)bh * LQ + (size_t)(i0 + rl)) * LK + j0 + nbase;
#pragma unroll
            for (int p = 0; p < 4; p++) {
                float s0x = acc[mm][2 * p][2 * h];
                float s0y = acc[mm][2 * p][2 * h + 1];
                float s1x = acc[mm][2 * p + 1][2 * h];
                float s1y = acc[mm][2 * p + 1][2 * h + 1];

                float a0x = __shfl_sync(0xffffffffu, s0x, d1);
                float a0y = __shfl_sync(0xffffffffu, s0y, d1);
                float b0x = __shfl_sync(0xffffffffu, s0x, d1 + 1);
                float b0y = __shfl_sync(0xffffffffu, s0y, d1 + 1);
                float a1x = __shfl_sync(0xffffffffu, s1x, d1);
                float a1y = __shfl_sync(0xffffffffu, s1y, d1);
                float b1x = __shfl_sync(0xffffffffu, s1x, d1 + 1);
                float b1y = __shfl_sync(0xffffffffu, s1y, d1 + 1);

                float4 v;
                if (tq < 2) { v.x = a0x; v.y = a0y; v.z = b0x; v.w = b0y; }
                else        { v.x = a1x; v.y = a1y; v.z = b1x; v.w = b1y; }

                const int c0 = p * 16 + tq * 4;
                const float* k2c = k2s + nbase + c0;
                v.x = q2v + k2c[0] - 2.0f * v.x;
                v.y = q2v + k2c[1] - 2.0f * v.y;
                v.z = q2v + k2c[2] - 2.0f * v.z;
                v.w = q2v + k2c[3] - 2.0f * v.w;
                *reinterpret_cast<float4*>(orow + c0) = v;
            }
        }
    }
}

// ---------------- Launch ----------------

extern "C" void kernel_launch(void* const* d_in, const int* in_sizes, int n_in,
                              void* d_out, int out_size) {
    const float* q = (const float*)d_in[0];   // [4,8,2048,64]
    const float* k = (const float*)d_in[1];   // [4,8,64,2048]
    float* out = (float*)d_out;               // [4,8,2048,2048]
    (void)in_sizes; (void)n_in; (void)out_size;

    dim3 grid(LK / TILE_N, LQ / TILE_M, 32);  // 16 x 16 x 32
    subgauss_kernel<<<grid, THREADS>>>(q, k, out);
}

// round 5
// speedup vs baseline: 1.6259x; 1.2617x over previous
#include <cuda_runtime.h>
#include <cuda_fp16.h>
#include <cstdint>

// ============================================================================
// SubtractionGaussian: out[b,h,i,j] = ||q_i||^2 + ||k_j||^2 - 2 q_i . k_j
// B*H = 32, Lq = Lk = 2048, D = 64, fp32 in/out.
//
// R5 = R4 resubmit (R4 failed on infra, not kernel):
//   slot-floor loads, free exact-fp32 k2, smem-staged 100%-efficient STG epilogue.
// ============================================================================

#define LQ 2048
#define LK 2048
#define DDIM 64
#define TILE_M 128
#define TILE_N 128
#define THREADS 256

#define QROW 72        // halfs per Qs row (144B; 9 granules == 1 mod 8 -> ldmatrix conflict-free)
#define KROW 136       // halfs per Ks row (272B; 17 granules == 1 mod 8 -> conflict-free)
#define SSTRIDE 72     // floats per stage row (288B; bank-period 8 -> floor phases)

__device__ __forceinline__ void mma16816(float* d, const uint32_t* a,
                                         uint32_t b0, uint32_t b1) {
    asm volatile(
        "mma.sync.aligned.m16n8k16.row.col.f32.f16.f16.f32 "
        "{%0,%1,%2,%3}, {%4,%5,%6,%7}, {%8,%9}, {%0,%1,%2,%3};"
        : "+f"(d[0]), "+f"(d[1]), "+f"(d[2]), "+f"(d[3])
        : "r"(a[0]), "r"(a[1]), "r"(a[2]), "r"(a[3]), "r"(b0), "r"(b1));
}

__device__ __forceinline__ void ldmatrix_x4(uint32_t* r, uint32_t addr) {
    asm volatile("ldmatrix.sync.aligned.m8n8.x4.shared.b16 {%0,%1,%2,%3}, [%4];"
                 : "=r"(r[0]), "=r"(r[1]), "=r"(r[2]), "=r"(r[3]) : "r"(addr));
}

__device__ __forceinline__ void ldmatrix_x4_trans(uint32_t* r, uint32_t addr) {
    asm volatile("ldmatrix.sync.aligned.m8n8.x4.trans.shared.b16 {%0,%1,%2,%3}, [%4];"
                 : "=r"(r[0]), "=r"(r[1]), "=r"(r[2]), "=r"(r[3]) : "r"(addr));
}

__global__ void __launch_bounds__(THREADS, 2)
subgauss_kernel(const float* __restrict__ q,   // [BH, Lq, D]
                const float* __restrict__ k,   // [BH, D, Lk]
                float* __restrict__ out)       // [BH, Lq, Lk]
{
    __shared__ __align__(16) __half Qs[TILE_M][QROW];   // 18432 B (re-used as stage)
    __shared__ __align__(16) __half Ks[DDIM][KROW];     // 17408 B
    __shared__ __align__(16) float q2s[TILE_M];
    __shared__ __align__(16) float k2s[TILE_N];
    __shared__ __align__(16) float kpart[8][TILE_N];    // 4096 B

    const int tid = threadIdx.x;
    const int lane = tid & 31;
    const int wid = tid >> 5;

    const int bh = blockIdx.z;
    const int i0 = blockIdx.y * TILE_M;
    const int j0 = blockIdx.x * TILE_N;

    // ---- Q load: 2 rows per warp-inst (16 lanes x float4, 512B contiguous). ----
    {
        const int hi = lane >> 4;          // 0/1 -> row parity
        const int seg2 = lane & 15;        // 16 lanes per row
#pragma unroll
        for (int p = 0; p < 8; p++) {
            const int r = wid * 2 + hi + p * 16;
            const float* qrow = q + ((size_t)bh * LQ + (size_t)(i0 + r)) * DDIM;
            float4 v = *reinterpret_cast<const float4*>(qrow + seg2 * 4);
            float s = v.x * v.x + v.y * v.y + v.z * v.z + v.w * v.w;
            s += __shfl_down_sync(0xffffffffu, s, 8, 16);
            s += __shfl_down_sync(0xffffffffu, s, 4, 16);
            s += __shfl_down_sync(0xffffffffu, s, 2, 16);
            s += __shfl_down_sync(0xffffffffu, s, 1, 16);
            if (seg2 == 0) q2s[r] = s;
            __half2 h01 = __floats2half2_rn(v.x, v.y);
            __half2 h23 = __floats2half2_rn(v.z, v.w);
            uint2 u;
            u.x = *reinterpret_cast<uint32_t*>(&h01);
            u.y = *reinterpret_cast<uint32_t*>(&h23);
            *reinterpret_cast<uint2*>(&Qs[r][seg2 * 4]) = u;
        }
    }

    // ---- K load: 1 c-row per warp-inst; exact fp32 k2 partials land for free. ----
    {
        const float* kb = k + (size_t)bh * DDIM * LK + (size_t)j0 + lane * 4;
        float4 ksum = make_float4(0.f, 0.f, 0.f, 0.f);
#pragma unroll
        for (int p = 0; p < 8; p++) {
            const int c = wid + p * 8;
            float4 v = *reinterpret_cast<const float4*>(kb + (size_t)c * LK);
            ksum.x += v.x * v.x; ksum.y += v.y * v.y;
            ksum.z += v.z * v.z; ksum.w += v.w * v.w;
            __half2 h01 = __floats2half2_rn(v.x, v.y);
            __half2 h23 = __floats2half2_rn(v.z, v.w);
            uint2 u;
            u.x = *reinterpret_cast<uint32_t*>(&h01);
            u.y = *reinterpret_cast<uint32_t*>(&h23);
            *reinterpret_cast<uint2*>(&Ks[c][lane * 4]) = u;
        }
        *reinterpret_cast<float4*>(&kpart[wid][lane * 4]) = ksum;
    }
    __syncthreads();

    // ---- k2 reduce: 128 threads sum 8 warp-partials (exact fp32). ----
    if (tid < TILE_N) {
        float s = 0.0f;
#pragma unroll
        for (int w = 0; w < 8; w++) s += kpart[w][tid];
        k2s[tid] = s;
    }

    // ---- Mainloop: warp (wm,wn) -> rows [wm*32,+32) x cols [wn*64,+64). ----
    const int wm = wid & 3;
    const int wn = wid >> 2;
    const int mbase = wm * 32;
    const int nbase = wn * 64;
    const int g = lane >> 3;      // ldmatrix quadrant
    const int lr = lane & 7;      // ldmatrix row

    float acc[2][8][4];
#pragma unroll
    for (int mm = 0; mm < 2; mm++)
#pragma unroll
        for (int nn = 0; nn < 8; nn++)
#pragma unroll
            for (int r = 0; r < 4; r++)
                acc[mm][nn][r] = 0.0f;

#pragma unroll
    for (int ks = 0; ks < 4; ks++) {
        uint32_t A[2][4];
#pragma unroll
        for (int mm = 0; mm < 2; mm++) {
            uint32_t addr = (uint32_t)__cvta_generic_to_shared(
                &Qs[mbase + mm * 16 + (g & 1) * 8 + lr][ks * 16 + (g >> 1) * 8]);
            ldmatrix_x4(A[mm], addr);
        }
#pragma unroll
        for (int e = 0; e < 4; e++) {
            uint32_t B[4];
            uint32_t addr = (uint32_t)__cvta_generic_to_shared(
                &Ks[ks * 16 + (g & 1) * 8 + lr][nbase + e * 16 + (g >> 1) * 8]);
            ldmatrix_x4_trans(B, addr);
            mma16816(acc[0][2 * e],     A[0], B[0], B[1]);
            mma16816(acc[1][2 * e],     A[1], B[0], B[1]);
            mma16816(acc[0][2 * e + 1], A[0], B[2], B[3]);
            mma16816(acc[1][2 * e + 1], A[1], B[2], B[3]);
        }
    }

    // ---- All warps done with Qs/Ks; re-use Qs as per-warp stage buffers. ----
    __syncthreads();

    {
        float* stg = reinterpret_cast<float*>(&Qs[0][0]) + wid * 8 * SSTRIDE;
        const int gq = lane >> 2;      // source row within slab
        const int tq = lane & 3;       // source col pair
        const int rr = lane >> 3;      // dest row within 4-row group
        const int cc = lane & 7;       // dest 16B chunk

        // preload k2 (fixed per lane) and q2 (8 rows per lane)
        float4 k2A = *reinterpret_cast<const float4*>(&k2s[nbase + cc * 4]);
        float4 k2B = *reinterpret_cast<const float4*>(&k2s[nbase + 32 + cc * 4]);
        float q2r[8];
#pragma unroll
        for (int mm = 0; mm < 2; mm++)
#pragma unroll
            for (int h = 0; h < 2; h++)
#pragma unroll
                for (int G = 0; G < 2; G++)
                    q2r[mm * 4 + h * 2 + G] = q2s[mbase + mm * 16 + h * 8 + G * 4 + rr];

#pragma unroll
        for (int mm = 0; mm < 2; mm++) {
#pragma unroll
            for (int h = 0; h < 2; h++) {
                __syncwarp();
                // scatter-free STS: rows gq, float2 per (nn,tq)
#pragma unroll
                for (int nn = 0; nn < 8; nn++) {
                    float2 f2;
                    f2.x = acc[mm][nn][2 * h];
                    f2.y = acc[mm][nn][2 * h + 1];
                    *reinterpret_cast<float2*>(&stg[gq * SSTRIDE + nn * 8 + tq * 2]) = f2;
                }
                __syncwarp();
                // coalesced LDS.128 + math + dense STG.128 (4 rows x 128B per inst)
#pragma unroll
                for (int s = 0; s < 4; s++) {
                    const int G = s >> 1;
                    const int C = s & 1;
                    float4 x = *reinterpret_cast<const float4*>(
                        &stg[(G * 4 + rr) * SSTRIDE + C * 32 + cc * 4]);
                    const float q2v = q2r[mm * 4 + h * 2 + G];
                    const float4 k2v = C ? k2B : k2A;
                    float4 o;
                    o.x = q2v + k2v.x - 2.0f * x.x;
                    o.y = q2v + k2v.y - 2.0f * x.y;
                    o.z = q2v + k2v.z - 2.0f * x.z;
                    o.w = q2v + k2v.w - 2.0f * x.w;
                    float* dst = out + ((size_t)bh * LQ +
                                        (size_t)(i0 + mbase + mm * 16 + h * 8 + G * 4 + rr)) * LK
                                     + j0 + nbase + C * 32 + cc * 4;
                    *reinterpret_cast<float4*>(dst) = o;
                }
            }
        }
    }
}

// ---------------- Launch ----------------

extern "C" void kernel_launch(void* const* d_in, const int* in_sizes, int n_in,
                              void* d_out, int out_size) {
    const float* q = (const float*)d_in[0];   // [4,8,2048,64]
    const float* k = (const float*)d_in[1];   // [4,8,64,2048]
    float* out = (float*)d_out;               // [4,8,2048,2048]
    (void)in_sizes; (void)n_in; (void)out_size;

    dim3 grid(LK / TILE_N, LQ / TILE_M, 32);  // 16 x 16 x 32
    subgauss_kernel<<<grid, THREADS>>>(q, k, out);
}